// round 13
// baseline (speedup 1.0000x reference)
#include <cuda_runtime.h>
#include <math.h>

#define NB 8
#define NH 256
#define NW 256
#define NPIX (NB*NH*NW)
#define NCH 8              // 8 chunks of 32 rows
#define NBLK 512           // grid size (all phases)
#define BLKB 64            // loss blocks per batch
#define THR 256

// Scratch (static __device__ per allocation rules)
__device__ unsigned g_bits[NB*NCH*NW];   // bit i of [b][c][j] = (mask(c*32+i, j) != 0)
__device__ float    g_absd[NPIX];        // |dist| = fgd + bgd (one of them is 0)
__device__ float2   g_rowmax[NB*NH];     // per-row (fg_max, bg_max)
__device__ float    g_part[NBLK*12];     // per-block partials: [0:4) focal, [4:8) inter, [8:12) (p+t)w
__device__ unsigned g_barA = 0;          // grid barrier A counter
__device__ unsigned g_barB = 0;          // grid barrier B counter
__device__ unsigned g_ctr  = 0;          // final-combine ticket

// Vertical distance to nearest set bit (after XOR with inv) in column jo at row h.
__device__ __forceinline__ float vdist(const unsigned* sw, int jo, int h,
                                       int c0, int b0, unsigned inv) {
    unsigned m = (sw[c0 * NW + jo] ^ inv) & (0xFFFFFFFFu >> (31 - b0));
    int c = c0;
    while (m == 0u && c > 0) m = sw[--c * NW + jo] ^ inv;
    int du = m ? h - (c * 32 + 31 - __clz(m)) : 100000;
    m = (sw[c0 * NW + jo] ^ inv) & (0xFFFFFFFFu << b0);
    c = c0;
    while (m == 0u && c < NCH - 1) m = sw[++c * NW + jo] ^ inv;
    int dd = m ? (c * 32 + __ffs(m) - 1) - h : 100000;
    int d = min(du, dd);
    return (d >= 100000) ? 1e6f : (float)d;
}

__device__ __forceinline__ void grid_barrier(unsigned* cnt, int tid) {
    __syncthreads();
    __threadfence();
    if (tid == 0) {
        atomicAdd(cnt, 1u);
        while (atomicAdd(cnt, 0u) < NBLK) __nanosleep(32);
    }
    __syncthreads();
}

__global__ __launch_bounds__(THR, 4)
void k_fused(const float* __restrict__ p0, const float* __restrict__ p1,
             const float* __restrict__ p2, const float* __restrict__ p3,
             const int* __restrict__ tg, float* __restrict__ out) {
    int blk = blockIdx.x;
    int tid = threadIdx.x;
    int lane = tid & 31, wq = tid >> 5;

    __shared__ unsigned sw[NCH * NW];      // 8 KB batch bitset
    __shared__ float sf[NW], sb[NW];
    __shared__ float smf[8], smb[8];

    // ===== Phase A: pack mask into per-column bitsets (blocks 0..63) =====
    if (blk < 64) {
        int w = blk * 8 + wq;                 // 512 warp-tiles
        int b = w >> 6, rem = w & 63, c = rem >> 3, jg = rem & 7;
        int j = jg * 32 + lane;
        const int* base = tg + (b * NH + c * 32) * NW + j;
        int v[32];
        #pragma unroll
        for (int i = 0; i < 32; ++i) v[i] = __ldg(base + i * NW);
        unsigned word = 0u;
        #pragma unroll
        for (int i = 0; i < 32; ++i) {
            unsigned bal = __ballot_sync(0xffffffffu, v[i] != 0);
            word |= ((bal >> lane) & 1u) << i;
        }
        g_bits[(b * NCH + c) * NW + j] = word;
    }

    grid_barrier(&g_barA, tid);

    // ===== Phase B: EDT, 4 rows per block; batch bitset staged once =====
    {
        int b = blk >> 6;
        int h0 = (blk & 63) * 4;
        #pragma unroll
        for (int c = 0; c < NCH; ++c)
            sw[c * NW + tid] = g_bits[(b * NCH + c) * NW + tid];
        __syncthreads();

        for (int i = 0; i < 4; ++i) {
            int h = h0 + i;
            int c0 = h >> 5, b0 = h & 31;
            float gf = vdist(sw, tid, h, c0, b0, 0xFFFFFFFFu);  // fg: mask==0
            float gb = vdist(sw, tid, h, c0, b0, 0u);           // bg: mask==1
            sf[tid] = gf;
            sb[tid] = gb;
            __syncthreads();

            float bf = gf * gf;
            float bb = gb * gb;
            for (int r = 1; r < NW; ++r) {
                float c = (float)(r * r);
                if (c >= bf && c >= bb) break;
                int jl = tid - r, jr = tid + r;
                if (jl >= 0) {
                    float a = sf[jl], x = sb[jl];
                    bf = fminf(bf, a * a + c);
                    bb = fminf(bb, x * x + c);
                }
                if (jr < NW) {
                    float a = sf[jr], x = sb[jr];
                    bf = fminf(bf, a * a + c);
                    bb = fminf(bb, x * x + c);
                }
            }
            float fgd = sqrtf(bf);
            float bgd = sqrtf(bb);
            g_absd[(b * NH + h) * NW + tid] = fgd + bgd;

            float mf = fgd, mb = bgd;
            #pragma unroll
            for (int o = 16; o; o >>= 1) {
                mf = fmaxf(mf, __shfl_down_sync(0xffffffffu, mf, o));
                mb = fmaxf(mb, __shfl_down_sync(0xffffffffu, mb, o));
            }
            if (lane == 0) { smf[wq] = mf; smb[wq] = mb; }
            __syncthreads();
            if (tid == 0) {
                #pragma unroll
                for (int q = 1; q < 8; ++q) { mf = fmaxf(mf, smf[q]); mb = fmaxf(mb, smb[q]); }
                g_rowmax[b * NH + h] = make_float2(mf, mb);
            }
            __syncthreads();   // protect sf/sb/smf/smb for next row
        }
    }

    grid_barrier(&g_barB, tid);

    // ===== Phase C: fused focal + IoU partials =====
    {
        int b = blk >> 6;

        __shared__ float sA[8], sB[8];
        {
            float2 rm = g_rowmax[b * NH + tid];
            float mf = rm.x, mb = rm.y;
            #pragma unroll
            for (int o = 16; o; o >>= 1) {
                mf = fmaxf(mf, __shfl_down_sync(0xffffffffu, mf, o));
                mb = fmaxf(mb, __shfl_down_sync(0xffffffffu, mb, o));
            }
            if (lane == 0) { sA[wq] = mf; sB[wq] = mb; }
        }
        __syncthreads();
        float mf = sA[0], mb = sB[0];
        #pragma unroll
        for (int q = 1; q < 8; ++q) { mf = fmaxf(mf, sA[q]); mb = fmaxf(mb, sB[q]); }
        float md = fmaxf(mf, mb);
        bool valid = (mb < 9e5f) && (md > 0.f);
        float inv3 = valid ? 3.0f / fmaxf(md, 1e-12f) : 0.f;
        float cfl  = valid ? 1.f : 0.f;

        int pix = b * (NH * NW) + (blk & 63) * 1024 + tid * 4;
        float4 x0 = *(const float4*)(p0 + pix);
        float4 x1 = *(const float4*)(p1 + pix);
        float4 x2 = *(const float4*)(p2 + pix);
        float4 x3 = *(const float4*)(p3 + pix);
        int4   tv = *(const int4*)(tg + pix);
        float4 ad = *(const float4*)(g_absd + pix);

        float X[4][4] = { {x0.x, x1.x, x2.x, x3.x},
                          {x0.y, x1.y, x2.y, x3.y},
                          {x0.z, x1.z, x2.z, x3.z},
                          {x0.w, x1.w, x2.w, x3.w} };
        float T[4]  = { (float)tv.x, (float)tv.y, (float)tv.z, (float)tv.w };
        float AD[4] = { ad.x, ad.y, ad.z, ad.w };

        float acc[12];
        #pragma unroll
        for (int k = 0; k < 12; ++k) acc[k] = 0.f;

        #pragma unroll
        for (int e = 0; e < 4; ++e) {
            float t = T[e];
            float w = 1.f + cfl * __expf(-AD[e] * inv3);
            float tw = t * w;
            float al = (t == 1.f) ? 0.25f : 0.75f;
            float s12 = 1.f - 2.f * t;
            #pragma unroll
            for (int k = 0; k < 4; ++k) {
                float x = X[e][k];
                float y = (t == 1.f) ? -x : x;
                float a = __expf(-fabsf(y));
                float ce = fmaxf(y, 0.f) + __logf(1.f + a);
                float r = __fdividef(1.f, 1.f + a);
                float q = ((y >= 0.f) ? 1.f : a) * r;     // sigmoid(y) = 1 - p_t
                acc[k] += al * q * q * ce;                 // focal
                float p = t + s12 * q;                     // sigmoid(x)
                float pw = p * w;
                acc[4 + k] += pw * t;                      // inter
                acc[8 + k] += pw + tw;                     // (p + t) * w
            }
        }

        #pragma unroll
        for (int k = 0; k < 12; ++k) {
            #pragma unroll
            for (int o = 16; o; o >>= 1)
                acc[k] += __shfl_down_sync(0xffffffffu, acc[k], o);
        }
        __shared__ float sred[8][12];
        if (lane == 0) {
            #pragma unroll
            for (int k = 0; k < 12; ++k) sred[wq][k] = acc[k];
        }
        __syncthreads();
        if (tid < 12) {
            float s = 0.f;
            #pragma unroll
            for (int q = 0; q < 8; ++q) s += sred[q][tid];
            g_part[blk * 12 + tid] = s;
        }
    }

    // ===== Ticket: last block does the deterministic final combine =====
    __threadfence();
    __syncthreads();
    __shared__ unsigned ticket;
    if (tid == 0) ticket = atomicAdd(&g_ctr, 1u);
    __syncthreads();
    if (ticket != NBLK - 1) return;
    __threadfence();

    __shared__ float s_iou[NB][4];
    __shared__ float sf4[4][THR];
    // IoU: warp wq handles batch wq
    {
        float in_[4] = {0.f,0.f,0.f,0.f}, u_[4] = {0.f,0.f,0.f,0.f};
        for (int r = lane; r < BLKB; r += 32) {
            const float* pp = g_part + (wq * BLKB + r) * 12;
            #pragma unroll
            for (int k = 0; k < 4; ++k) { in_[k] += pp[4 + k]; u_[k] += pp[8 + k]; }
        }
        #pragma unroll
        for (int k = 0; k < 4; ++k) {
            #pragma unroll
            for (int o = 16; o; o >>= 1) {
                in_[k] += __shfl_down_sync(0xffffffffu, in_[k], o);
                u_[k]  += __shfl_down_sync(0xffffffffu, u_[k],  o);
            }
        }
        if (lane == 0) {
            #pragma unroll
            for (int k = 0; k < 4; ++k) {
                float inter = in_[k];
                float un = u_[k] - inter;
                s_iou[wq][k] = (inter + 1e-6f) / (un + 1e-6f);
            }
        }
    }

    // Focal: tree reduce over NBLK block-partials
    float f[4] = {0.f,0.f,0.f,0.f};
    for (int i = tid; i < NBLK; i += THR) {
        const float* pp = g_part + i * 12;
        #pragma unroll
        for (int k = 0; k < 4; ++k) f[k] += pp[k];
    }
    #pragma unroll
    for (int k = 0; k < 4; ++k) sf4[k][tid] = f[k];
    __syncthreads();
    for (int s = 128; s; s >>= 1) {
        if (tid < s) {
            #pragma unroll
            for (int k = 0; k < 4; ++k) sf4[k][tid] += sf4[k][tid + s];
        }
        __syncthreads();
    }

    if (tid == 0) {
        const float wgt[4] = { 1.0f, 0.4f, 0.2f, 0.4f / 3.0f };
        float total = 0.f;
        #pragma unroll
        for (int k = 0; k < 4; ++k) {
            float fm = sf4[k][0] / (float)NPIX;
            float is = 0.f;
            #pragma unroll
            for (int b2 = 0; b2 < NB; ++b2) is += s_iou[b2][k];
            float il = 1.f - is / (float)NB;
            total += wgt[k] * (fm + il);
        }
        out[0] = total;
        // reset counters for the next graph replay
        g_barA = 0u;
        g_barB = 0u;
        g_ctr  = 0u;
    }
}

extern "C" void kernel_launch(void* const* d_in, const int* in_sizes, int n_in,
                              void* d_out, int out_size) {
    const float* p0 = (const float*)d_in[0];   // pred_main
    const float* p1 = (const float*)d_in[1];   // aux0
    const float* p2 = (const float*)d_in[2];   // aux1
    const float* p3 = (const float*)d_in[3];   // aux2
    const int*   tg = (const int*)d_in[4];     // targets

    k_fused<<<NBLK, THR>>>(p0, p1, p2, p3, tg, (float*)d_out);
}

// round 14
// speedup vs baseline: 1.0120x; 1.0120x over previous
#include <cuda_runtime.h>
#include <math.h>

#define NB 8
#define NH 256
#define NW 256
#define NPIX (NB*NH*NW)
#define NCH 8              // 8 chunks of 32 rows
#define NBLK 512           // grid size (all phases)
#define BLKB 64            // loss blocks per batch
#define THR 256

// Scratch (static __device__ per allocation rules)
__device__ unsigned g_bits[NB*NCH*NW];   // bit i of [b][c][j] = (mask(c*32+i, j) != 0)
__device__ float2   g_rowmax[NB*NH];     // per-row (fg_max, bg_max)
__device__ float    g_part[NBLK*12];     // per-block partials: [0:4) focal, [4:8) inter, [8:12) (p+t)w
__device__ unsigned g_barA = 0;          // grid barrier A counter
__device__ unsigned g_barB = 0;          // grid barrier B counter
__device__ unsigned g_ctr  = 0;          // final-combine ticket

// Vertical distance to nearest set bit (after XOR with inv) in column jo at row h.
__device__ __forceinline__ float vdist(const unsigned* sw, int jo, int h,
                                       int c0, int b0, unsigned inv) {
    unsigned m = (sw[c0 * NW + jo] ^ inv) & (0xFFFFFFFFu >> (31 - b0));
    int c = c0;
    while (m == 0u && c > 0) m = sw[--c * NW + jo] ^ inv;
    int du = m ? h - (c * 32 + 31 - __clz(m)) : 100000;
    m = (sw[c0 * NW + jo] ^ inv) & (0xFFFFFFFFu << b0);
    c = c0;
    while (m == 0u && c < NCH - 1) m = sw[++c * NW + jo] ^ inv;
    int dd = m ? (c * 32 + __ffs(m) - 1) - h : 100000;
    int d = min(du, dd);
    return (d >= 100000) ? 1e6f : (float)d;
}

__device__ __forceinline__ void grid_barrier(unsigned* cnt, int tid) {
    __syncthreads();
    __threadfence();
    if (tid == 0) {
        atomicAdd(cnt, 1u);
        while (atomicAdd(cnt, 0u) < NBLK) __nanosleep(32);
    }
    __syncthreads();
}

__global__ __launch_bounds__(THR, 4)
void k_fused(const float* __restrict__ p0, const float* __restrict__ p1,
             const float* __restrict__ p2, const float* __restrict__ p3,
             const int* __restrict__ tg, float* __restrict__ out) {
    int blk = blockIdx.x;
    int tid = threadIdx.x;
    int lane = tid & 31, wq = tid >> 5;
    int b = blk >> 6;

    __shared__ unsigned sw[NCH * NW];      // 8 KB batch bitset
    __shared__ float sf[NW], sb[NW];
    __shared__ float smf[8], smb[8];
    __shared__ float s_absd[4 * NW];       // this block's 4 rows of |dist|

    // ===== Phase A: pack mask into per-column bitsets (blocks 0..63) =====
    if (blk < 64) {
        int w = blk * 8 + wq;                 // 512 warp-tiles
        int bb = w >> 6, rem = w & 63, c = rem >> 3, jg = rem & 7;
        int j = jg * 32 + lane;
        const int* base = tg + (bb * NH + c * 32) * NW + j;
        int v[32];
        #pragma unroll
        for (int i = 0; i < 32; ++i) v[i] = __ldg(base + i * NW);
        unsigned word = 0u;
        #pragma unroll
        for (int i = 0; i < 32; ++i) {
            unsigned bal = __ballot_sync(0xffffffffu, v[i] != 0);
            word |= ((bal >> lane) & 1u) << i;
        }
        g_bits[(bb * NCH + c) * NW + j] = word;
    }

    // ===== Prefetch phase-C operands (independent of A/B) =====
    int pix = b * (NH * NW) + (blk & 63) * 1024 + tid * 4;
    float4 x0 = *(const float4*)(p0 + pix);
    float4 x1 = *(const float4*)(p1 + pix);
    float4 x2 = *(const float4*)(p2 + pix);
    float4 x3 = *(const float4*)(p3 + pix);
    int4   tv = *(const int4*)(tg + pix);

    grid_barrier(&g_barA, tid);

    // ===== Phase B: EDT, 4 rows per block; |dist| kept in smem =====
    {
        int h0 = (blk & 63) * 4;
        #pragma unroll
        for (int c = 0; c < NCH; ++c)
            sw[c * NW + tid] = g_bits[(b * NCH + c) * NW + tid];
        __syncthreads();

        for (int i = 0; i < 4; ++i) {
            int h = h0 + i;
            int c0 = h >> 5, b0 = h & 31;
            float gf = vdist(sw, tid, h, c0, b0, 0xFFFFFFFFu);  // fg: mask==0
            float gb = vdist(sw, tid, h, c0, b0, 0u);           // bg: mask==1
            sf[tid] = gf;
            sb[tid] = gb;
            __syncthreads();

            float bf = gf * gf;
            float bb2 = gb * gb;
            for (int r = 1; r < NW; ++r) {
                float c = (float)(r * r);
                if (c >= bf && c >= bb2) break;
                int jl = tid - r, jr = tid + r;
                if (jl >= 0) {
                    float a = sf[jl], x = sb[jl];
                    bf = fminf(bf, a * a + c);
                    bb2 = fminf(bb2, x * x + c);
                }
                if (jr < NW) {
                    float a = sf[jr], x = sb[jr];
                    bf = fminf(bf, a * a + c);
                    bb2 = fminf(bb2, x * x + c);
                }
            }
            float fgd = sqrtf(bf);
            float bgd = sqrtf(bb2);
            s_absd[i * NW + tid] = fgd + bgd;

            float mf = fgd, mb = bgd;
            #pragma unroll
            for (int o = 16; o; o >>= 1) {
                mf = fmaxf(mf, __shfl_down_sync(0xffffffffu, mf, o));
                mb = fmaxf(mb, __shfl_down_sync(0xffffffffu, mb, o));
            }
            if (lane == 0) { smf[wq] = mf; smb[wq] = mb; }
            __syncthreads();
            if (tid == 0) {
                #pragma unroll
                for (int q = 1; q < 8; ++q) { mf = fmaxf(mf, smf[q]); mb = fmaxf(mb, smb[q]); }
                g_rowmax[b * NH + h] = make_float2(mf, mb);
            }
            __syncthreads();   // protect sf/sb/smf/smb for next row
        }
    }

    grid_barrier(&g_barB, tid);

    // ===== Phase C: fused focal + IoU partials =====
    {
        __shared__ float sA[8], sB[8];
        {
            float2 rm = g_rowmax[b * NH + tid];
            float mf = rm.x, mb = rm.y;
            #pragma unroll
            for (int o = 16; o; o >>= 1) {
                mf = fmaxf(mf, __shfl_down_sync(0xffffffffu, mf, o));
                mb = fmaxf(mb, __shfl_down_sync(0xffffffffu, mb, o));
            }
            if (lane == 0) { sA[wq] = mf; sB[wq] = mb; }
        }
        __syncthreads();
        float mf = sA[0], mb = sB[0];
        #pragma unroll
        for (int q = 1; q < 8; ++q) { mf = fmaxf(mf, sA[q]); mb = fmaxf(mb, sB[q]); }
        float md = fmaxf(mf, mb);
        bool valid = (mb < 9e5f) && (md > 0.f);
        float inv3 = valid ? 3.0f / fmaxf(md, 1e-12f) : 0.f;
        float cfl  = valid ? 1.f : 0.f;

        float X[4][4] = { {x0.x, x1.x, x2.x, x3.x},
                          {x0.y, x1.y, x2.y, x3.y},
                          {x0.z, x1.z, x2.z, x3.z},
                          {x0.w, x1.w, x2.w, x3.w} };
        float T[4]  = { (float)tv.x, (float)tv.y, (float)tv.z, (float)tv.w };
        // |dist| for this thread's 4 pixels: row tid>>6, cols (tid&63)*4 ..
        int rbase = (tid >> 6) * NW + (tid & 63) * 4;
        float AD[4] = { s_absd[rbase], s_absd[rbase + 1],
                        s_absd[rbase + 2], s_absd[rbase + 3] };

        float acc[12];
        #pragma unroll
        for (int k = 0; k < 12; ++k) acc[k] = 0.f;

        #pragma unroll
        for (int e = 0; e < 4; ++e) {
            float t = T[e];
            float w = 1.f + cfl * __expf(-AD[e] * inv3);
            float tw = t * w;
            float al = (t == 1.f) ? 0.25f : 0.75f;
            float s12 = 1.f - 2.f * t;
            #pragma unroll
            for (int k = 0; k < 4; ++k) {
                float x = X[e][k];
                float y = (t == 1.f) ? -x : x;
                float a = __expf(-fabsf(y));
                float ce = fmaxf(y, 0.f) + __logf(1.f + a);
                float r = __fdividef(1.f, 1.f + a);
                float q = ((y >= 0.f) ? 1.f : a) * r;     // sigmoid(y) = 1 - p_t
                acc[k] += al * q * q * ce;                 // focal
                float p = t + s12 * q;                     // sigmoid(x)
                float pw = p * w;
                acc[4 + k] += pw * t;                      // inter
                acc[8 + k] += pw + tw;                     // (p + t) * w
            }
        }

        #pragma unroll
        for (int k = 0; k < 12; ++k) {
            #pragma unroll
            for (int o = 16; o; o >>= 1)
                acc[k] += __shfl_down_sync(0xffffffffu, acc[k], o);
        }
        __shared__ float sred[8][12];
        if (lane == 0) {
            #pragma unroll
            for (int k = 0; k < 12; ++k) sred[wq][k] = acc[k];
        }
        __syncthreads();
        if (tid < 12) {
            float s = 0.f;
            #pragma unroll
            for (int q = 0; q < 8; ++q) s += sred[q][tid];
            g_part[blk * 12 + tid] = s;
        }
    }

    // ===== Ticket: last block does the deterministic final combine =====
    __threadfence();
    __syncthreads();
    __shared__ unsigned ticket;
    if (tid == 0) ticket = atomicAdd(&g_ctr, 1u);
    __syncthreads();
    if (ticket != NBLK - 1) return;
    __threadfence();

    __shared__ float s_iou[NB][4];
    __shared__ float sf4[4][THR];
    // IoU: warp wq handles batch wq
    {
        float in_[4] = {0.f,0.f,0.f,0.f}, u_[4] = {0.f,0.f,0.f,0.f};
        for (int r = lane; r < BLKB; r += 32) {
            const float* pp = g_part + (wq * BLKB + r) * 12;
            #pragma unroll
            for (int k = 0; k < 4; ++k) { in_[k] += pp[4 + k]; u_[k] += pp[8 + k]; }
        }
        #pragma unroll
        for (int k = 0; k < 4; ++k) {
            #pragma unroll
            for (int o = 16; o; o >>= 1) {
                in_[k] += __shfl_down_sync(0xffffffffu, in_[k], o);
                u_[k]  += __shfl_down_sync(0xffffffffu, u_[k],  o);
            }
        }
        if (lane == 0) {
            #pragma unroll
            for (int k = 0; k < 4; ++k) {
                float inter = in_[k];
                float un = u_[k] - inter;
                s_iou[wq][k] = (inter + 1e-6f) / (un + 1e-6f);
            }
        }
    }

    // Focal: tree reduce over NBLK block-partials
    float f[4] = {0.f,0.f,0.f,0.f};
    for (int i = tid; i < NBLK; i += THR) {
        const float* pp = g_part + i * 12;
        #pragma unroll
        for (int k = 0; k < 4; ++k) f[k] += pp[k];
    }
    #pragma unroll
    for (int k = 0; k < 4; ++k) sf4[k][tid] = f[k];
    __syncthreads();
    for (int s = 128; s; s >>= 1) {
        if (tid < s) {
            #pragma unroll
            for (int k = 0; k < 4; ++k) sf4[k][tid] += sf4[k][tid + s];
        }
        __syncthreads();
    }

    if (tid == 0) {
        const float wgt[4] = { 1.0f, 0.4f, 0.2f, 0.4f / 3.0f };
        float total = 0.f;
        #pragma unroll
        for (int k = 0; k < 4; ++k) {
            float fm = sf4[k][0] / (float)NPIX;
            float is = 0.f;
            #pragma unroll
            for (int b2 = 0; b2 < NB; ++b2) is += s_iou[b2][k];
            float il = 1.f - is / (float)NB;
            total += wgt[k] * (fm + il);
        }
        out[0] = total;
        // reset counters for the next graph replay
        g_barA = 0u;
        g_barB = 0u;
        g_ctr  = 0u;
    }
}

extern "C" void kernel_launch(void* const* d_in, const int* in_sizes, int n_in,
                              void* d_out, int out_size) {
    const float* p0 = (const float*)d_in[0];   // pred_main
    const float* p1 = (const float*)d_in[1];   // aux0
    const float* p2 = (const float*)d_in[2];   // aux1
    const float* p3 = (const float*)d_in[3];   // aux2
    const int*   tg = (const int*)d_in[4];     // targets

    k_fused<<<NBLK, THR>>>(p0, p1, p2, p3, tg, (float*)d_out);
}

// round 15
// speedup vs baseline: 1.0136x; 1.0015x over previous
#include <cuda_runtime.h>
#include <math.h>

#define NB 8
#define NH 256
#define NW 256
#define NPIX (NB*NH*NW)
#define NCH 8              // 8 chunks of 32 rows
#define NBLK 512           // grid size
#define BLKB 64            // blocks per batch
#define THR 256

// Scratch (static __device__ per allocation rules)
__device__ unsigned g_bits[NB*NCH*NW];   // bit i of [b][c][j] = (mask(c*32+i, j) != 0)
__device__ float2   g_rowmax[NB*NH];     // per-row (fg_max, bg_max)
__device__ float    g_part[NBLK*12];     // per-block partials
__device__ unsigned g_barA[NB];          // per-batch barrier A (pack done)
__device__ unsigned g_barB[NB];          // per-batch barrier B (edt done)
__device__ unsigned g_ctr = 0;           // final-combine ticket

// Vertical distance to nearest set bit (after XOR with inv) in column jo at row h.
__device__ __forceinline__ float vdist(const unsigned* sw, int jo, int h,
                                       int c0, int b0, unsigned inv) {
    unsigned m = (sw[c0 * NW + jo] ^ inv) & (0xFFFFFFFFu >> (31 - b0));
    int c = c0;
    while (m == 0u && c > 0) m = sw[--c * NW + jo] ^ inv;
    int du = m ? h - (c * 32 + 31 - __clz(m)) : 100000;
    m = (sw[c0 * NW + jo] ^ inv) & (0xFFFFFFFFu << b0);
    c = c0;
    while (m == 0u && c < NCH - 1) m = sw[++c * NW + jo] ^ inv;
    int dd = m ? (c * 32 + __ffs(m) - 1) - h : 100000;
    int d = min(du, dd);
    return (d >= 100000) ? 1e6f : (float)d;
}

__device__ __forceinline__ void batch_barrier(unsigned* cnt, int tid) {
    __syncthreads();
    __threadfence();
    if (tid == 0) {
        atomicAdd(cnt, 1u);
        volatile unsigned* vc = (volatile unsigned*)cnt;
        while (*vc < BLKB) __nanosleep(32);
    }
    __syncthreads();
}

__global__ __launch_bounds__(THR, 4)
void k_fused(const float* __restrict__ p0, const float* __restrict__ p1,
             const float* __restrict__ p2, const float* __restrict__ p3,
             const int* __restrict__ tg, float* __restrict__ out) {
    int blk = blockIdx.x;
    int tid = threadIdx.x;
    int lane = tid & 31, wq = tid >> 5;
    int b = blk >> 6;
    int rem = blk & 63;

    __shared__ unsigned sw[NCH * NW];         // 8 KB batch bitset
    __shared__ unsigned s_rowbits[32];        // phase A: per-row ballots
    __shared__ float sf4[4][NW], sb4[4][NW];  // 4 rows of vertical distances
    __shared__ float s_absd[4 * NW];          // 4 rows of |dist|
    __shared__ float smf[4][8], smb[4][8];

    // ===== Phase A: every block packs ONE 32x32 tile (8 warps, 4 rows each) =====
    {
        int c = rem >> 3, jg = rem & 7;       // chunk, column-group
        int r0 = wq * 4;
        #pragma unroll
        for (int i = 0; i < 4; ++i) {
            int r = r0 + i;
            int val = tg[(b * NH + c * 32 + r) * NW + jg * 32 + lane];
            unsigned bal = __ballot_sync(0xffffffffu, val != 0);
            if (lane == 0) s_rowbits[r] = bal;
        }
        __syncthreads();
        if (tid < 32) {
            unsigned word = 0u;
            #pragma unroll
            for (int r = 0; r < 32; ++r)
                word |= ((s_rowbits[r] >> tid) & 1u) << r;
            g_bits[(b * NCH + c) * NW + jg * 32 + tid] = word;
        }
    }

    // ===== Prefetch phase-C operands (independent of A/B) =====
    int pix = b * (NH * NW) + rem * 1024 + tid * 4;
    float4 x0 = *(const float4*)(p0 + pix);
    float4 x1 = *(const float4*)(p1 + pix);
    float4 x2 = *(const float4*)(p2 + pix);
    float4 x3 = *(const float4*)(p3 + pix);
    int4   tv = *(const int4*)(tg + pix);

    batch_barrier(&g_barA[b], tid);

    // ===== Phase B: EDT, 4 rows per block; 3 syncs total =====
    {
        int h0 = rem * 4;
        #pragma unroll
        for (int c = 0; c < NCH; ++c)
            sw[c * NW + tid] = g_bits[(b * NCH + c) * NW + tid];
        __syncthreads();

        #pragma unroll
        for (int i = 0; i < 4; ++i) {
            int h = h0 + i;
            int c0 = h >> 5, b0 = h & 31;
            sf4[i][tid] = vdist(sw, tid, h, c0, b0, 0xFFFFFFFFu);  // fg: mask==0
            sb4[i][tid] = vdist(sw, tid, h, c0, b0, 0u);           // bg: mask==1
        }
        __syncthreads();

        #pragma unroll
        for (int i = 0; i < 4; ++i) {
            float gf = sf4[i][tid], gb = sb4[i][tid];
            float bf = gf * gf;
            float bb2 = gb * gb;
            for (int r = 1; r < NW; ++r) {
                float c = (float)(r * r);
                if (c >= bf && c >= bb2) break;
                int jl = tid - r, jr = tid + r;
                if (jl >= 0) {
                    float a = sf4[i][jl], x = sb4[i][jl];
                    bf = fminf(bf, a * a + c);
                    bb2 = fminf(bb2, x * x + c);
                }
                if (jr < NW) {
                    float a = sf4[i][jr], x = sb4[i][jr];
                    bf = fminf(bf, a * a + c);
                    bb2 = fminf(bb2, x * x + c);
                }
            }
            float fgd = sqrtf(bf);
            float bgd = sqrtf(bb2);
            s_absd[i * NW + tid] = fgd + bgd;

            float mf = fgd, mb = bgd;
            #pragma unroll
            for (int o = 16; o; o >>= 1) {
                mf = fmaxf(mf, __shfl_down_sync(0xffffffffu, mf, o));
                mb = fmaxf(mb, __shfl_down_sync(0xffffffffu, mb, o));
            }
            if (lane == 0) { smf[i][wq] = mf; smb[i][wq] = mb; }
        }
        __syncthreads();
        if (tid < 4) {
            float mf = smf[tid][0], mb = smb[tid][0];
            #pragma unroll
            for (int q = 1; q < 8; ++q) {
                mf = fmaxf(mf, smf[tid][q]);
                mb = fmaxf(mb, smb[tid][q]);
            }
            g_rowmax[b * NH + h0 + tid] = make_float2(mf, mb);
        }
    }

    batch_barrier(&g_barB[b], tid);

    // ===== Phase C: fused focal + IoU partials =====
    {
        __shared__ float sA[8], sB[8];
        {
            float2 rm = g_rowmax[b * NH + tid];
            float mf = rm.x, mb = rm.y;
            #pragma unroll
            for (int o = 16; o; o >>= 1) {
                mf = fmaxf(mf, __shfl_down_sync(0xffffffffu, mf, o));
                mb = fmaxf(mb, __shfl_down_sync(0xffffffffu, mb, o));
            }
            if (lane == 0) { sA[wq] = mf; sB[wq] = mb; }
        }
        __syncthreads();
        float mf = sA[0], mb = sB[0];
        #pragma unroll
        for (int q = 1; q < 8; ++q) { mf = fmaxf(mf, sA[q]); mb = fmaxf(mb, sB[q]); }
        float md = fmaxf(mf, mb);
        bool valid = (mb < 9e5f) && (md > 0.f);
        float inv3 = valid ? 3.0f / fmaxf(md, 1e-12f) : 0.f;
        float cfl  = valid ? 1.f : 0.f;

        float X[4][4] = { {x0.x, x1.x, x2.x, x3.x},
                          {x0.y, x1.y, x2.y, x3.y},
                          {x0.z, x1.z, x2.z, x3.z},
                          {x0.w, x1.w, x2.w, x3.w} };
        float T[4]  = { (float)tv.x, (float)tv.y, (float)tv.z, (float)tv.w };
        int rbase = (tid >> 6) * NW + (tid & 63) * 4;
        float AD[4] = { s_absd[rbase], s_absd[rbase + 1],
                        s_absd[rbase + 2], s_absd[rbase + 3] };

        float acc[12];
        #pragma unroll
        for (int k = 0; k < 12; ++k) acc[k] = 0.f;

        #pragma unroll
        for (int e = 0; e < 4; ++e) {
            float t = T[e];
            float w = 1.f + cfl * __expf(-AD[e] * inv3);
            float tw = t * w;
            float al = (t == 1.f) ? 0.25f : 0.75f;
            float s12 = 1.f - 2.f * t;
            #pragma unroll
            for (int k = 0; k < 4; ++k) {
                float x = X[e][k];
                float y = (t == 1.f) ? -x : x;
                float a = __expf(-fabsf(y));
                float ce = fmaxf(y, 0.f) + __logf(1.f + a);
                float r = __fdividef(1.f, 1.f + a);
                float q = ((y >= 0.f) ? 1.f : a) * r;     // sigmoid(y) = 1 - p_t
                acc[k] += al * q * q * ce;                 // focal
                float p = t + s12 * q;                     // sigmoid(x)
                float pw = p * w;
                acc[4 + k] += pw * t;                      // inter
                acc[8 + k] += pw + tw;                     // (p + t) * w
            }
        }

        #pragma unroll
        for (int k = 0; k < 12; ++k) {
            #pragma unroll
            for (int o = 16; o; o >>= 1)
                acc[k] += __shfl_down_sync(0xffffffffu, acc[k], o);
        }
        __shared__ float sred[8][12];
        if (lane == 0) {
            #pragma unroll
            for (int k = 0; k < 12; ++k) sred[wq][k] = acc[k];
        }
        __syncthreads();
        if (tid < 12) {
            float s = 0.f;
            #pragma unroll
            for (int q = 0; q < 8; ++q) s += sred[q][tid];
            g_part[blk * 12 + tid] = s;
        }
    }

    // ===== Ticket: last block does the deterministic final combine =====
    __threadfence();
    __syncthreads();
    __shared__ unsigned ticket;
    if (tid == 0) ticket = atomicAdd(&g_ctr, 1u);
    __syncthreads();
    if (ticket != NBLK - 1) return;
    __threadfence();

    __shared__ float s_iou[NB][4];
    __shared__ float sfin[4][THR];
    // IoU: warp wq handles batch wq
    {
        float in_[4] = {0.f,0.f,0.f,0.f}, u_[4] = {0.f,0.f,0.f,0.f};
        for (int r = lane; r < BLKB; r += 32) {
            const float* pp = g_part + (wq * BLKB + r) * 12;
            #pragma unroll
            for (int k = 0; k < 4; ++k) { in_[k] += pp[4 + k]; u_[k] += pp[8 + k]; }
        }
        #pragma unroll
        for (int k = 0; k < 4; ++k) {
            #pragma unroll
            for (int o = 16; o; o >>= 1) {
                in_[k] += __shfl_down_sync(0xffffffffu, in_[k], o);
                u_[k]  += __shfl_down_sync(0xffffffffu, u_[k],  o);
            }
        }
        if (lane == 0) {
            #pragma unroll
            for (int k = 0; k < 4; ++k) {
                float inter = in_[k];
                float un = u_[k] - inter;
                s_iou[wq][k] = (inter + 1e-6f) / (un + 1e-6f);
            }
        }
    }

    // Focal: tree reduce over NBLK block-partials
    float f[4] = {0.f,0.f,0.f,0.f};
    for (int i = tid; i < NBLK; i += THR) {
        const float* pp = g_part + i * 12;
        #pragma unroll
        for (int k = 0; k < 4; ++k) f[k] += pp[k];
    }
    #pragma unroll
    for (int k = 0; k < 4; ++k) sfin[k][tid] = f[k];
    __syncthreads();
    for (int s = 128; s; s >>= 1) {
        if (tid < s) {
            #pragma unroll
            for (int k = 0; k < 4; ++k) sfin[k][tid] += sfin[k][tid + s];
        }
        __syncthreads();
    }

    if (tid == 0) {
        const float wgt[4] = { 1.0f, 0.4f, 0.2f, 0.4f / 3.0f };
        float total = 0.f;
        #pragma unroll
        for (int k = 0; k < 4; ++k) {
            float fm = sfin[k][0] / (float)NPIX;
            float is = 0.f;
            #pragma unroll
            for (int b2 = 0; b2 < NB; ++b2) is += s_iou[b2][k];
            float il = 1.f - is / (float)NB;
            total += wgt[k] * (fm + il);
        }
        out[0] = total;
        // reset counters for the next graph replay
        #pragma unroll
        for (int q = 0; q < NB; ++q) { g_barA[q] = 0u; g_barB[q] = 0u; }
        g_ctr = 0u;
    }
}

extern "C" void kernel_launch(void* const* d_in, const int* in_sizes, int n_in,
                              void* d_out, int out_size) {
    const float* p0 = (const float*)d_in[0];   // pred_main
    const float* p1 = (const float*)d_in[1];   // aux0
    const float* p2 = (const float*)d_in[2];   // aux1
    const float* p3 = (const float*)d_in[3];   // aux2
    const int*   tg = (const int*)d_in[4];     // targets

    k_fused<<<NBLK, THR>>>(p0, p1, p2, p3, tg, (float*)d_out);
}